// round 9
// baseline (speedup 1.0000x reference)
#include <cuda_runtime.h>
#include <cuda_fp16.h>
#include <cstdint>

// ============================================================================
// y = x @ W_mod^T ; W_mod = W with values*0.1 scattered at flip_idx (last wins)
// x:[256,4096] f32, W:[4096,4096] f32, flip:[1M] int32, vals:[1M] f32 -> y f32
// Pipeline: stage1 [winner(u64 packed tokens) | x->f16 | W->f16 swizzled]
//           -> exchange-scatter (no vals gather) -> TMA-fed HMMA GEMM
// ============================================================================

#define O_DIM  4096
#define I_DIM  4096
#define B_ROWS 256
#define W_ELEMS (O_DIM * I_DIM)
#define X_ELEMS (B_ROWS * I_DIM)

#define SW128(b) ((b) ^ (((b) >> 3) & 0x70))

// Chunk-major swizzled layouts (K-chunk = 128 cols = 256B, two 128B sub-tiles):
//  g_xh: [chunk 32][m_tile 2][ sub0 16KB | sub1 16KB ]          (64KB/chunk)
//  g_wh: [chunk 32][n_tile 64][ sub0 8KB | sub1 8KB ]           (1MB/chunk)
__device__ __align__(16) __half g_xh[X_ELEMS];
__device__ __align__(16) __half g_wh[W_ELEMS];
// packed winner tokens: ((i+1)<<32) | f16bits(vals[i]*0.1). Zero at module
// load; atomicExch in scatter restores the all-zero invariant every launch.
__device__ unsigned long long g_aux[W_ELEMS];

// ----------------------------------------------------------------------------
// Stage 1: fused [winner election | x convert | W convert]
// ----------------------------------------------------------------------------
static constexpr int NB_WIN = 977;                 // ceil(1e6/1024), 4 idx/thr
static constexpr int NB_CX  = X_ELEMS / 4 / 256;   // 1024
static constexpr int NB_CW  = W_ELEMS / 4 / 256;   // 16384

__device__ __forceinline__ unsigned long long pack_tok(int i, float v) {
    return ((unsigned long long)(unsigned)(i + 1) << 32)
         | (unsigned long long)__half_as_ushort(__float2half_rn(v * 0.1f));
}

__global__ void __launch_bounds__(256) stage1_kernel(
    const float4* __restrict__ x, const float4* __restrict__ w,
    const int* __restrict__ flip, const float* __restrict__ vals, int n) {
    const int bid = blockIdx.x, tid = threadIdx.x;
    if (bid < NB_WIN) {
        const int base = bid * 1024 + tid * 4;
        if (base + 3 < n) {
            const int4 f = *reinterpret_cast<const int4*>(flip + base);
            const float4 v = *reinterpret_cast<const float4*>(vals + base);
            atomicMax(&g_aux[f.x], pack_tok(base + 0, v.x));
            atomicMax(&g_aux[f.y], pack_tok(base + 1, v.y));
            atomicMax(&g_aux[f.z], pack_tok(base + 2, v.z));
            atomicMax(&g_aux[f.w], pack_tok(base + 3, v.w));
        } else {
            for (int k = 0; k < 4; ++k)
                if (base + k < n)
                    atomicMax(&g_aux[flip[base + k]], pack_tok(base + k, vals[base + k]));
        }
    } else if (bid < NB_WIN + NB_CX) {
        const int i = (bid - NB_WIN) * 256 + tid;
        const int m = i >> 10, kq = (i & 1023) << 2;      // 4 k-elems
        float4 v = x[i];
        uint2 p = make_uint2(
            (uint32_t)__half_as_ushort(__float2half_rn(v.x)) |
            ((uint32_t)__half_as_ushort(__float2half_rn(v.y)) << 16),
            (uint32_t)__half_as_ushort(__float2half_rn(v.z)) |
            ((uint32_t)__half_as_ushort(__float2half_rn(v.w)) << 16));
        const int c = kq >> 7, k0 = kq & 127, sub = k0 >> 6, kk = k0 & 63;
        char* dst = reinterpret_cast<char*>(g_xh)
                  + (size_t)c * 65536 + (m >> 7) * 32768 + sub * 16384
                  + SW128((m & 127) * 128 + kk * 2);
        *reinterpret_cast<uint2*>(dst) = p;
    } else {
        const int i = (bid - NB_WIN - NB_CX) * 256 + tid;
        const int o = i >> 10, kq = (i & 1023) << 2;
        float4 v = w[i];
        uint2 p = make_uint2(
            (uint32_t)__half_as_ushort(__float2half_rn(v.x)) |
            ((uint32_t)__half_as_ushort(__float2half_rn(v.y)) << 16),
            (uint32_t)__half_as_ushort(__float2half_rn(v.z)) |
            ((uint32_t)__half_as_ushort(__float2half_rn(v.w)) << 16));
        const int c = kq >> 7, k0 = kq & 127, sub = k0 >> 6, kk = k0 & 63;
        char* dst = reinterpret_cast<char*>(g_wh)
                  + (size_t)c * 1048576 + (o >> 6) * 16384 + sub * 8192
                  + SW128((o & 63) * 128 + kk * 2);
        *reinterpret_cast<uint2*>(dst) = p;
    }
}

// ----------------------------------------------------------------------------
// Stage 2: exchange-scatter (value carried in the token; no vals gather)
// ----------------------------------------------------------------------------
__device__ __forceinline__ void scatter_one(int pos, unsigned short hbits) {
    const int o = pos >> 12, k = pos & 4095;
    const int c = k >> 7, k0 = k & 127, sub = k0 >> 6, kk = k0 & 63;
    char* dst = reinterpret_cast<char*>(g_wh)
              + (size_t)c * 1048576 + (o >> 6) * 16384 + sub * 8192
              + SW128((o & 63) * 128 + kk * 2);
    *reinterpret_cast<unsigned short*>(dst) = hbits;
}

__global__ void __launch_bounds__(256) scatter_kernel(
    const int* __restrict__ flip, int n) {
    const int base = (blockIdx.x * 256 + threadIdx.x) * 4;
    if (base + 3 < n) {
        const int4 f = *reinterpret_cast<const int4*>(flip + base);
        int pos[4] = {f.x, f.y, f.z, f.w};
        unsigned long long old[4];
        #pragma unroll
        for (int k = 0; k < 4; ++k) old[k] = atomicExch(&g_aux[pos[k]], 0ULL);
        #pragma unroll
        for (int k = 0; k < 4; ++k)
            if (old[k]) scatter_one(pos[k], (unsigned short)(old[k] & 0xFFFF));
    } else {
        for (int k = 0; k < 4; ++k)
            if (base + k < n) {
                int p = flip[base + k];
                unsigned long long o = atomicExch(&g_aux[p], 0ULL);
                if (o) scatter_one(p, (unsigned short)(o & 0xFFFF));
            }
    }
}

// ============================================================================
// Stage 3: GEMM. CTA 128x64, K-chunk 128, 3-deep TMA bulk pipeline with
// full/empty mbarriers (no per-chunk __syncthreads).
// ============================================================================
static constexpr int A_SUB = 16384;   // A sub-tile: 128 rows x 128B
static constexpr int B_OFF = 32768;
static constexpr int B_SUB = 8192;    // B sub-tile: 64 rows x 128B
static constexpr int BUF   = 49152;
static constexpr int SM_TILES = 1024; // mbarriers live below
static constexpr int GEMM_SMEM = SM_TILES + 3 * BUF;   // 148480
static constexpr int NC    = I_DIM / 128;   // 32 chunks

__device__ __forceinline__ uint32_t smem_u32(const void* p) {
    uint32_t a;
    asm("{ .reg .u64 t; cvta.to.shared.u64 t, %1; cvt.u32.u64 %0, t; }"
        : "=r"(a) : "l"(p));
    return a;
}
__device__ __forceinline__ void ldsm4(uint32_t* r, uint32_t addr) {
    asm volatile("ldmatrix.sync.aligned.m8n8.x4.shared.b16 {%0,%1,%2,%3}, [%4];"
                 : "=r"(r[0]), "=r"(r[1]), "=r"(r[2]), "=r"(r[3]) : "r"(addr));
}
__device__ __forceinline__ void mma16816(float* c, const uint32_t* a,
                                         uint32_t b0, uint32_t b1) {
    asm volatile(
        "mma.sync.aligned.m16n8k16.row.col.f32.f16.f16.f32 "
        "{%0,%1,%2,%3}, {%4,%5,%6,%7}, {%8,%9}, {%0,%1,%2,%3};"
        : "+f"(c[0]), "+f"(c[1]), "+f"(c[2]), "+f"(c[3])
        : "r"(a[0]), "r"(a[1]), "r"(a[2]), "r"(a[3]), "r"(b0), "r"(b1));
}

#define MBAR_WAIT(mbar_addr, phase) do {                                         \
    uint32_t _mbar = (uint32_t)(mbar_addr);                                      \
    uint32_t _parity = (uint32_t)(phase);                                        \
    uint32_t _done;                                                              \
    asm volatile(                                                                \
        "{\n\t.reg .pred p;\n\t"                                                 \
        "mbarrier.try_wait.parity.acquire.cta.shared::cta.b64 p, [%1], %2;\n\t"  \
        "selp.b32 %0, 1, 0, p;\n\t}"                                             \
        : "=r"(_done) : "r"(_mbar), "r"(_parity) : "memory");                    \
    if (!_done) {                                                                \
        asm volatile(                                                            \
            "{\n\t.reg .pred P1;\n\t"                                            \
            "WL_%=:\n\t"                                                         \
            "mbarrier.try_wait.parity.acquire.cta.shared::cta.b64 P1, [%0], %1, 0x989680;\n\t" \
            "@P1 bra.uni WD_%=;\n\t"                                             \
            "bra.uni WL_%=;\n\t"                                                 \
            "WD_%=:\n\t}"                                                        \
            :: "r"(_mbar), "r"(_parity) : "memory");                             \
    }                                                                            \
} while (0)

// Issue A(32KB) + B(16KB) bulk copies for chunk c into buffer (single thread).
__device__ __forceinline__ void tma_chunk(uint32_t bufb, uint32_t mbar,
                                          int c, int m0, int n0) {
    asm volatile("mbarrier.arrive.expect_tx.shared.b64 _, [%0], %1;"
                 :: "r"(mbar), "r"(49152u) : "memory");
    const char* srcA = reinterpret_cast<const char*>(g_xh)
                     + (size_t)c * 65536 + (m0 >> 7) * 32768;
    const char* srcB = reinterpret_cast<const char*>(g_wh)
                     + (size_t)c * 1048576 + (n0 >> 6) * 16384;
    asm volatile(
        "cp.async.bulk.shared::cluster.global.mbarrier::complete_tx::bytes "
        "[%0], [%1], %2, [%3];"
        :: "r"(bufb), "l"(srcA), "r"(32768u), "r"(mbar) : "memory");
    asm volatile(
        "cp.async.bulk.shared::cluster.global.mbarrier::complete_tx::bytes "
        "[%0], [%1], %2, [%3];"
        :: "r"(bufb + B_OFF), "l"(srcB), "r"(16384u), "r"(mbar) : "memory");
}

__global__ void __launch_bounds__(256, 1) gemm_kernel(float* __restrict__ y) {
    extern __shared__ __align__(1024) char smem[];
    const uint32_t sb = smem_u32(smem);
    const int tid = threadIdx.x, lane = tid & 31, wid = tid >> 5;
    const int wm = wid >> 1, wn = wid & 1;          // warp grid 4(M) x 2(N)
    const int n0 = blockIdx.x * 64;
    const int m0 = blockIdx.y * 128;

    // full[b] at sb + b*8 (count 1, tx); empty[b] at sb + 24 + b*8 (count 8)
    if (tid == 0) {
        #pragma unroll
        for (int b = 0; b < 3; ++b) {
            asm volatile("mbarrier.init.shared.b64 [%0], 1;"
                         :: "r"(sb + b * 8) : "memory");
            asm volatile("mbarrier.init.shared.b64 [%0], 8;"
                         :: "r"(sb + 24 + b * 8) : "memory");
        }
    }
    __syncthreads();
    if (tid == 0) {
        tma_chunk(sb + SM_TILES + 0 * BUF, sb + 0,  0, m0, n0);
        tma_chunk(sb + SM_TILES + 1 * BUF, sb + 8,  1, m0, n0);
        tma_chunk(sb + SM_TILES + 2 * BUF, sb + 16, 2, m0, n0);
    }

    float acc[2][4][4];
    #pragma unroll
    for (int i = 0; i < 2; ++i)
        #pragma unroll
        for (int j = 0; j < 4; ++j)
            #pragma unroll
            for (int q = 0; q < 4; ++q) acc[i][j][q] = 0.f;

    const int rl = lane & 15, kh = lane >> 4;
    const uint32_t arow0 = (uint32_t)(wm * 32 + rl) * 128;
    const uint32_t arow1 = arow0 + 16 * 128;
    const uint32_t brow0 = (uint32_t)(wn * 32 + rl) * 128;
    const uint32_t brow1 = brow0 + 16 * 128;

    for (int c = 0; c < NC; ++c) {
        const int b = c % 3;
        const uint32_t ph = (uint32_t)((c / 3) & 1);
        MBAR_WAIT(sb + b * 8, ph);
        const uint32_t bb = sb + SM_TILES + b * BUF;

        #pragma unroll
        for (int ks = 0; ks < 8; ++ks) {
            const uint32_t sub_a = bb + (ks >> 2) * A_SUB;
            const uint32_t sub_b = bb + B_OFF + (ks >> 2) * B_SUB;
            const uint32_t kb = (uint32_t)(ks & 3) * 32 + (uint32_t)kh * 16;
            uint32_t ah[2][4], bh[2][4];
            ldsm4(ah[0], sub_a + SW128(arow0 + kb));
            ldsm4(ah[1], sub_a + SW128(arow1 + kb));
            ldsm4(bh[0], sub_b + SW128(brow0 + kb));
            ldsm4(bh[1], sub_b + SW128(brow1 + kb));
            #pragma unroll
            for (int mi = 0; mi < 2; ++mi)
                #pragma unroll
                for (int nj = 0; nj < 2; ++nj) {
                    mma16816(acc[mi][nj*2+0], ah[mi], bh[nj][0], bh[nj][2]);
                    mma16816(acc[mi][nj*2+1], ah[mi], bh[nj][1], bh[nj][3]);
                }
        }
        // per-warp arrive on empty[b]; producer waits all 8 before reusing b
        if (lane == 0)
            asm volatile("mbarrier.arrive.shared.b64 _, [%0];"
                         :: "r"(sb + 24 + b * 8) : "memory");
        if (tid == 0 && c + 3 < NC) {
            MBAR_WAIT(sb + 24 + b * 8, ph);
            tma_chunk(sb + SM_TILES + b * BUF, sb + b * 8, c + 3, m0, n0);
        }
    }

    #pragma unroll
    for (int mi = 0; mi < 2; ++mi) {
        const int row0 = m0 + wm * 32 + mi * 16 + (lane >> 2);
        #pragma unroll
        for (int nb = 0; nb < 4; ++nb) {
            const int col = n0 + wn * 32 + nb * 8 + (lane & 3) * 2;
            *reinterpret_cast<float2*>(y + (size_t)row0 * O_DIM + col) =
                make_float2(acc[mi][nb][0], acc[mi][nb][1]);
            *reinterpret_cast<float2*>(y + (size_t)(row0 + 8) * O_DIM + col) =
                make_float2(acc[mi][nb][2], acc[mi][nb][3]);
        }
    }
}

// ============================================================================
extern "C" void kernel_launch(void* const* d_in, const int* in_sizes, int n_in,
                              void* d_out, int out_size) {
    const float* x    = (const float*)d_in[0];
    const float* w    = (const float*)d_in[1];
    const int*   flip = (const int*)d_in[2];   // JAX x64 disabled -> int32
    const float* vals = (const float*)d_in[3];
    float*       y    = (float*)d_out;
    const int nflip = in_sizes[2];

    stage1_kernel<<<NB_WIN + NB_CX + NB_CW, 256>>>(
        reinterpret_cast<const float4*>(x), reinterpret_cast<const float4*>(w),
        flip, vals, nflip);
    scatter_kernel<<<(nflip + 1023) / 1024, 256>>>(flip, nflip);

    cudaFuncSetAttribute(gemm_kernel, cudaFuncAttributeMaxDynamicSharedMemorySize,
                         GEMM_SMEM);
    gemm_kernel<<<dim3(O_DIM / 64, B_ROWS / 128, 1), 256, GEMM_SMEM>>>(y);
}

// round 10
// speedup vs baseline: 1.2359x; 1.2359x over previous
#include <cuda_runtime.h>
#include <cuda_fp16.h>
#include <cstdint>

// ============================================================================
// y = x @ W_mod^T ; W_mod = W with values*0.1 scattered at flip_idx (last wins)
// x:[256,4096] f32, W:[4096,4096] f32, flip:[1M] int32, vals:[1M] f32 -> y f32
// R8 architecture (proven 98.8us): stage1 [winner | x->f16 | W->f16, both in
// chunk-major PRE-SWIZZLED layout] -> exchange-scatter -> TMA-bulk-fed HMMA.
// R10 deltas: scatter MLP 4->8, streaming cache hints in stage1.
// ============================================================================

#define O_DIM  4096
#define I_DIM  4096
#define B_ROWS 256
#define W_ELEMS (O_DIM * I_DIM)
#define X_ELEMS (B_ROWS * I_DIM)

#define SW128(b) ((b) ^ (((b) >> 3) & 0x70))

// Chunk-major swizzled layouts (K-chunk = 128 cols = 256B, two 128B sub-tiles):
//  g_xh: [chunk 32][m_tile 2][ sub0 16KB | sub1 16KB ]          (64KB/chunk)
//  g_wh: [chunk 32][n_tile 64][ sub0 8KB | sub1 8KB ]           (1MB/chunk)
__device__ __align__(16) __half g_xh[X_ELEMS];
__device__ __align__(16) __half g_wh[W_ELEMS];
// zero at module load; atomicExch in scatter restores all-zero every launch
__device__ int g_aux[W_ELEMS];

// ----------------------------------------------------------------------------
// Stage 1: fused [winner election | x convert | W convert]
// ----------------------------------------------------------------------------
static constexpr int NB_WIN = 977;                 // ceil(1e6/1024), 4 idx/thr
static constexpr int NB_CX  = X_ELEMS / 4 / 256;   // 1024
static constexpr int NB_CW  = W_ELEMS / 4 / 256;   // 16384

__global__ void __launch_bounds__(256) stage1_kernel(
    const float4* __restrict__ x, const float4* __restrict__ w,
    const int* __restrict__ flip, int n) {
    const int bid = blockIdx.x, tid = threadIdx.x;
    if (bid < NB_WIN) {
        const int base = bid * 1024 + tid * 4;
        if (base + 3 < n) {
            const int4 f = *reinterpret_cast<const int4*>(flip + base);
            atomicMax(&g_aux[f.x], base + 1);
            atomicMax(&g_aux[f.y], base + 2);
            atomicMax(&g_aux[f.z], base + 3);
            atomicMax(&g_aux[f.w], base + 4);
        } else {
            for (int k = 0; k < 4; ++k)
                if (base + k < n) atomicMax(&g_aux[flip[base + k]], base + k + 1);
        }
    } else if (bid < NB_WIN + NB_CX) {
        const int i = (bid - NB_WIN) * 256 + tid;
        const int m = i >> 10, kq = (i & 1023) << 2;      // 4 k-elems
        float4 v = __ldcs(x + i);
        uint2 p = make_uint2(
            (uint32_t)__half_as_ushort(__float2half_rn(v.x)) |
            ((uint32_t)__half_as_ushort(__float2half_rn(v.y)) << 16),
            (uint32_t)__half_as_ushort(__float2half_rn(v.z)) |
            ((uint32_t)__half_as_ushort(__float2half_rn(v.w)) << 16));
        const int c = kq >> 7, k0 = kq & 127, sub = k0 >> 6, kk = k0 & 63;
        char* dst = reinterpret_cast<char*>(g_xh)
                  + (size_t)c * 65536 + (m >> 7) * 32768 + sub * 16384
                  + SW128((m & 127) * 128 + kk * 2);
        __stcs(reinterpret_cast<uint2*>(dst), p);
    } else {
        const int i = (bid - NB_WIN - NB_CX) * 256 + tid;
        const int o = i >> 10, kq = (i & 1023) << 2;
        float4 v = __ldcs(w + i);
        uint2 p = make_uint2(
            (uint32_t)__half_as_ushort(__float2half_rn(v.x)) |
            ((uint32_t)__half_as_ushort(__float2half_rn(v.y)) << 16),
            (uint32_t)__half_as_ushort(__float2half_rn(v.z)) |
            ((uint32_t)__half_as_ushort(__float2half_rn(v.w)) << 16));
        const int c = kq >> 7, k0 = kq & 127, sub = k0 >> 6, kk = k0 & 63;
        char* dst = reinterpret_cast<char*>(g_wh)
                  + (size_t)c * 1048576 + (o >> 6) * 16384 + sub * 8192
                  + SW128((o & 63) * 128 + kk * 2);
        __stcs(reinterpret_cast<uint2*>(dst), p);
    }
}

// ----------------------------------------------------------------------------
// Stage 2: exchange-scatter into the swizzled W layout (8 idx/thread for MLP)
// ----------------------------------------------------------------------------
__device__ __forceinline__ void scatter_one(int pos, float v) {
    const int o = pos >> 12, k = pos & 4095;
    const int c = k >> 7, k0 = k & 127, sub = k0 >> 6, kk = k0 & 63;
    char* dst = reinterpret_cast<char*>(g_wh)
              + (size_t)c * 1048576 + (o >> 6) * 16384 + sub * 8192
              + SW128((o & 63) * 128 + kk * 2);
    *reinterpret_cast<__half*>(dst) = __float2half_rn(v);
}

__global__ void __launch_bounds__(256) scatter_kernel(
    const int* __restrict__ flip, const float* __restrict__ vals, int n) {
    const int base = (blockIdx.x * 256 + threadIdx.x) * 8;
    if (base + 7 < n) {
        const int4 f0 = *reinterpret_cast<const int4*>(flip + base);
        const int4 f1 = *reinterpret_cast<const int4*>(flip + base + 4);
        int pos[8] = {f0.x, f0.y, f0.z, f0.w, f1.x, f1.y, f1.z, f1.w};
        int old[8];
        #pragma unroll
        for (int k = 0; k < 8; ++k) old[k] = atomicExch(&g_aux[pos[k]], 0);
        #pragma unroll
        for (int k = 0; k < 8; ++k)
            if (old[k]) scatter_one(pos[k], vals[old[k] - 1] * 0.1f);
    } else {
        for (int k = 0; k < 8; ++k)
            if (base + k < n) {
                int p = flip[base + k];
                int o = atomicExch(&g_aux[p], 0);
                if (o) scatter_one(p, vals[o - 1] * 0.1f);
            }
    }
}

// ============================================================================
// Stage 3: GEMM. CTA 128x64, K-chunk 128, 3-deep TMA bulk pipeline (R8-exact).
// ============================================================================
static constexpr int A_SUB = 16384;   // A sub-tile: 128 rows x 128B
static constexpr int B_OFF = 32768;
static constexpr int B_SUB = 8192;    // B sub-tile: 64 rows x 128B
static constexpr int BUF   = 49152;
static constexpr int SM_TILES = 1024; // mbarriers live below
static constexpr int GEMM_SMEM = SM_TILES + 3 * BUF;   // 148480
static constexpr int NC    = I_DIM / 128;   // 32 chunks

__device__ __forceinline__ uint32_t smem_u32(const void* p) {
    uint32_t a;
    asm("{ .reg .u64 t; cvta.to.shared.u64 t, %1; cvt.u32.u64 %0, t; }"
        : "=r"(a) : "l"(p));
    return a;
}
__device__ __forceinline__ void ldsm4(uint32_t* r, uint32_t addr) {
    asm volatile("ldmatrix.sync.aligned.m8n8.x4.shared.b16 {%0,%1,%2,%3}, [%4];"
                 : "=r"(r[0]), "=r"(r[1]), "=r"(r[2]), "=r"(r[3]) : "r"(addr));
}
__device__ __forceinline__ void mma16816(float* c, const uint32_t* a,
                                         uint32_t b0, uint32_t b1) {
    asm volatile(
        "mma.sync.aligned.m16n8k16.row.col.f32.f16.f16.f32 "
        "{%0,%1,%2,%3}, {%4,%5,%6,%7}, {%8,%9}, {%0,%1,%2,%3};"
        : "+f"(c[0]), "+f"(c[1]), "+f"(c[2]), "+f"(c[3])
        : "r"(a[0]), "r"(a[1]), "r"(a[2]), "r"(a[3]), "r"(b0), "r"(b1));
}

#define MBAR_WAIT(mbar_addr, phase) do {                                         \
    uint32_t _mbar = (uint32_t)(mbar_addr);                                      \
    uint32_t _parity = (uint32_t)(phase);                                        \
    uint32_t _done;                                                              \
    asm volatile(                                                                \
        "{\n\t.reg .pred p;\n\t"                                                 \
        "mbarrier.try_wait.parity.acquire.cta.shared::cta.b64 p, [%1], %2;\n\t"  \
        "selp.b32 %0, 1, 0, p;\n\t}"                                             \
        : "=r"(_done) : "r"(_mbar), "r"(_parity) : "memory");                    \
    if (!_done) {                                                                \
        asm volatile(                                                            \
            "{\n\t.reg .pred P1;\n\t"                                            \
            "WL_%=:\n\t"                                                         \
            "mbarrier.try_wait.parity.acquire.cta.shared::cta.b64 P1, [%0], %1, 0x989680;\n\t" \
            "@P1 bra.uni WD_%=;\n\t"                                             \
            "bra.uni WL_%=;\n\t"                                                 \
            "WD_%=:\n\t}"                                                        \
            :: "r"(_mbar), "r"(_parity) : "memory");                             \
    }                                                                            \
} while (0)

// Issue A(32KB) + B(16KB) bulk copies for chunk c into buffer (single thread).
__device__ __forceinline__ void tma_chunk(uint32_t bufb, uint32_t mbar,
                                          int c, int m0, int n0) {
    asm volatile("mbarrier.arrive.expect_tx.shared.b64 _, [%0], %1;"
                 :: "r"(mbar), "r"(49152u) : "memory");
    const char* srcA = reinterpret_cast<const char*>(g_xh)
                     + (size_t)c * 65536 + (m0 >> 7) * 32768;
    const char* srcB = reinterpret_cast<const char*>(g_wh)
                     + (size_t)c * 1048576 + (n0 >> 6) * 16384;
    asm volatile(
        "cp.async.bulk.shared::cluster.global.mbarrier::complete_tx::bytes "
        "[%0], [%1], %2, [%3];"
        :: "r"(bufb), "l"(srcA), "r"(32768u), "r"(mbar) : "memory");
    asm volatile(
        "cp.async.bulk.shared::cluster.global.mbarrier::complete_tx::bytes "
        "[%0], [%1], %2, [%3];"
        :: "r"(bufb + B_OFF), "l"(srcB), "r"(16384u), "r"(mbar) : "memory");
}

__global__ void __launch_bounds__(256, 1) gemm_kernel(float* __restrict__ y) {
    extern __shared__ __align__(1024) char smem[];
    const uint32_t sb = smem_u32(smem);
    const int tid = threadIdx.x, lane = tid & 31, wid = tid >> 5;
    const int wm = wid >> 1, wn = wid & 1;          // warp grid 4(M) x 2(N)
    const int n0 = blockIdx.x * 64;
    const int m0 = blockIdx.y * 128;

    if (tid == 0) {
        asm volatile("mbarrier.init.shared.b64 [%0], 1;" :: "r"(sb + 0) : "memory");
        asm volatile("mbarrier.init.shared.b64 [%0], 1;" :: "r"(sb + 8) : "memory");
        asm volatile("mbarrier.init.shared.b64 [%0], 1;" :: "r"(sb + 16) : "memory");
    }
    __syncthreads();
    if (tid == 0) {
        tma_chunk(sb + SM_TILES + 0 * BUF, sb + 0,  0, m0, n0);
        tma_chunk(sb + SM_TILES + 1 * BUF, sb + 8,  1, m0, n0);
        tma_chunk(sb + SM_TILES + 2 * BUF, sb + 16, 2, m0, n0);
    }

    float acc[2][4][4];
    #pragma unroll
    for (int i = 0; i < 2; ++i)
        #pragma unroll
        for (int j = 0; j < 4; ++j)
            #pragma unroll
            for (int q = 0; q < 4; ++q) acc[i][j][q] = 0.f;

    const int rl = lane & 15, kh = lane >> 4;
    const uint32_t arow0 = (uint32_t)(wm * 32 + rl) * 128;
    const uint32_t arow1 = arow0 + 16 * 128;
    const uint32_t brow0 = (uint32_t)(wn * 32 + rl) * 128;
    const uint32_t brow1 = brow0 + 16 * 128;

    for (int c = 0; c < NC; ++c) {
        const int b = c % 3;
        MBAR_WAIT(sb + b * 8, (c / 3) & 1);
        const uint32_t bb = sb + SM_TILES + b * BUF;

        #pragma unroll
        for (int ks = 0; ks < 8; ++ks) {
            const uint32_t sub_a = bb + (ks >> 2) * A_SUB;
            const uint32_t sub_b = bb + B_OFF + (ks >> 2) * B_SUB;
            const uint32_t kb = (uint32_t)(ks & 3) * 32 + (uint32_t)kh * 16;
            uint32_t ah[2][4], bh[2][4];
            ldsm4(ah[0], sub_a + SW128(arow0 + kb));
            ldsm4(ah[1], sub_a + SW128(arow1 + kb));
            ldsm4(bh[0], sub_b + SW128(brow0 + kb));
            ldsm4(bh[1], sub_b + SW128(brow1 + kb));
            #pragma unroll
            for (int mi = 0; mi < 2; ++mi)
                #pragma unroll
                for (int nj = 0; nj < 2; ++nj) {
                    mma16816(acc[mi][nj*2+0], ah[mi], bh[nj][0], bh[nj][2]);
                    mma16816(acc[mi][nj*2+1], ah[mi], bh[nj][1], bh[nj][3]);
                }
        }
        __syncthreads();   // all warps done with buffer b
        if (tid == 0 && c + 3 < NC)
            tma_chunk(sb + SM_TILES + b * BUF, sb + b * 8, c + 3, m0, n0);
    }

    #pragma unroll
    for (int mi = 0; mi < 2; ++mi) {
        const int row0 = m0 + wm * 32 + mi * 16 + (lane >> 2);
        #pragma unroll
        for (int nb = 0; nb < 4; ++nb) {
            const int col = n0 + wn * 32 + nb * 8 + (lane & 3) * 2;
            *reinterpret_cast<float2*>(y + (size_t)row0 * O_DIM + col) =
                make_float2(acc[mi][nb][0], acc[mi][nb][1]);
            *reinterpret_cast<float2*>(y + (size_t)(row0 + 8) * O_DIM + col) =
                make_float2(acc[mi][nb][2], acc[mi][nb][3]);
        }
    }
}

// ============================================================================
extern "C" void kernel_launch(void* const* d_in, const int* in_sizes, int n_in,
                              void* d_out, int out_size) {
    const float* x    = (const float*)d_in[0];
    const float* w    = (const float*)d_in[1];
    const int*   flip = (const int*)d_in[2];   // JAX x64 disabled -> int32
    const float* vals = (const float*)d_in[3];
    float*       y    = (float*)d_out;
    const int nflip = in_sizes[2];

    stage1_kernel<<<NB_WIN + NB_CX + NB_CW, 256>>>(
        reinterpret_cast<const float4*>(x), reinterpret_cast<const float4*>(w),
        flip, nflip);
    scatter_kernel<<<(nflip + 2047) / 2048, 256>>>(flip, vals, nflip);

    cudaFuncSetAttribute(gemm_kernel, cudaFuncAttributeMaxDynamicSharedMemorySize,
                         GEMM_SMEM);
    gemm_kernel<<<dim3(O_DIM / 64, B_ROWS / 128, 1), 256, GEMM_SMEM>>>(y);
}

// round 11
// speedup vs baseline: 1.2444x; 1.0069x over previous
#include <cuda_runtime.h>
#include <cuda_fp16.h>
#include <cstdint>

// ============================================================================
// y = x @ W_mod^T ; W_mod = W with values*0.1 scattered at flip_idx (last wins)
// x:[256,4096] f32, W:[4096,4096] f32, flip:[1M] int32, vals:[1M] f32 -> y f32
// stage1 [winner | x->f16 | W->f16 chunk-major pre-swizzled] -> exch-scatter
// -> TMA-bulk GEMM (R11: reg-double-buffered ldsm pipeline, 4-deep TMA)
// ============================================================================

#define O_DIM  4096
#define I_DIM  4096
#define B_ROWS 256
#define W_ELEMS (O_DIM * I_DIM)
#define X_ELEMS (B_ROWS * I_DIM)

#define SW128(b) ((b) ^ (((b) >> 3) & 0x70))

// Chunk-major swizzled layouts (K-chunk = 128 cols = 256B, two 128B sub-tiles):
//  g_xh: [chunk 32][m_tile 2][ sub0 16KB | sub1 16KB ]          (64KB/chunk)
//  g_wh: [chunk 32][n_tile 64][ sub0 8KB | sub1 8KB ]           (1MB/chunk)
__device__ __align__(16) __half g_xh[X_ELEMS];
__device__ __align__(16) __half g_wh[W_ELEMS];
// zero at module load; atomicExch in scatter restores all-zero every launch
__device__ int g_aux[W_ELEMS];

// ----------------------------------------------------------------------------
// Stage 1: fused [winner election | x convert | W convert]  (R10-exact)
// ----------------------------------------------------------------------------
static constexpr int NB_WIN = 977;                 // ceil(1e6/1024), 4 idx/thr
static constexpr int NB_CX  = X_ELEMS / 4 / 256;   // 1024
static constexpr int NB_CW  = W_ELEMS / 4 / 256;   // 16384

__global__ void __launch_bounds__(256) stage1_kernel(
    const float4* __restrict__ x, const float4* __restrict__ w,
    const int* __restrict__ flip, int n) {
    const int bid = blockIdx.x, tid = threadIdx.x;
    if (bid < NB_WIN) {
        const int base = bid * 1024 + tid * 4;
        if (base + 3 < n) {
            const int4 f = *reinterpret_cast<const int4*>(flip + base);
            atomicMax(&g_aux[f.x], base + 1);
            atomicMax(&g_aux[f.y], base + 2);
            atomicMax(&g_aux[f.z], base + 3);
            atomicMax(&g_aux[f.w], base + 4);
        } else {
            for (int k = 0; k < 4; ++k)
                if (base + k < n) atomicMax(&g_aux[flip[base + k]], base + k + 1);
        }
    } else if (bid < NB_WIN + NB_CX) {
        const int i = (bid - NB_WIN) * 256 + tid;
        const int m = i >> 10, kq = (i & 1023) << 2;      // 4 k-elems
        float4 v = __ldcs(x + i);
        uint2 p = make_uint2(
            (uint32_t)__half_as_ushort(__float2half_rn(v.x)) |
            ((uint32_t)__half_as_ushort(__float2half_rn(v.y)) << 16),
            (uint32_t)__half_as_ushort(__float2half_rn(v.z)) |
            ((uint32_t)__half_as_ushort(__float2half_rn(v.w)) << 16));
        const int c = kq >> 7, k0 = kq & 127, sub = k0 >> 6, kk = k0 & 63;
        char* dst = reinterpret_cast<char*>(g_xh)
                  + (size_t)c * 65536 + (m >> 7) * 32768 + sub * 16384
                  + SW128((m & 127) * 128 + kk * 2);
        __stcs(reinterpret_cast<uint2*>(dst), p);
    } else {
        const int i = (bid - NB_WIN - NB_CX) * 256 + tid;
        const int o = i >> 10, kq = (i & 1023) << 2;
        float4 v = __ldcs(w + i);
        uint2 p = make_uint2(
            (uint32_t)__half_as_ushort(__float2half_rn(v.x)) |
            ((uint32_t)__half_as_ushort(__float2half_rn(v.y)) << 16),
            (uint32_t)__half_as_ushort(__float2half_rn(v.z)) |
            ((uint32_t)__half_as_ushort(__float2half_rn(v.w)) << 16));
        const int c = kq >> 7, k0 = kq & 127, sub = k0 >> 6, kk = k0 & 63;
        char* dst = reinterpret_cast<char*>(g_wh)
                  + (size_t)c * 1048576 + (o >> 6) * 16384 + sub * 8192
                  + SW128((o & 63) * 128 + kk * 2);
        __stcs(reinterpret_cast<uint2*>(dst), p);
    }
}

// ----------------------------------------------------------------------------
// Stage 2: exchange-scatter (8 idx/thread, R10-exact)
// ----------------------------------------------------------------------------
__device__ __forceinline__ void scatter_one(int pos, float v) {
    const int o = pos >> 12, k = pos & 4095;
    const int c = k >> 7, k0 = k & 127, sub = k0 >> 6, kk = k0 & 63;
    char* dst = reinterpret_cast<char*>(g_wh)
              + (size_t)c * 1048576 + (o >> 6) * 16384 + sub * 8192
              + SW128((o & 63) * 128 + kk * 2);
    *reinterpret_cast<__half*>(dst) = __float2half_rn(v);
}

__global__ void __launch_bounds__(256) scatter_kernel(
    const int* __restrict__ flip, const float* __restrict__ vals, int n) {
    const int base = (blockIdx.x * 256 + threadIdx.x) * 8;
    if (base + 7 < n) {
        const int4 f0 = *reinterpret_cast<const int4*>(flip + base);
        const int4 f1 = *reinterpret_cast<const int4*>(flip + base + 4);
        int pos[8] = {f0.x, f0.y, f0.z, f0.w, f1.x, f1.y, f1.z, f1.w};
        int old[8];
        #pragma unroll
        for (int k = 0; k < 8; ++k) old[k] = atomicExch(&g_aux[pos[k]], 0);
        #pragma unroll
        for (int k = 0; k < 8; ++k)
            if (old[k]) scatter_one(pos[k], vals[old[k] - 1] * 0.1f);
    } else {
        for (int k = 0; k < 8; ++k)
            if (base + k < n) {
                int p = flip[base + k];
                int o = atomicExch(&g_aux[p], 0);
                if (o) scatter_one(p, vals[o - 1] * 0.1f);
            }
    }
}

// ============================================================================
// Stage 3: GEMM. CTA 128x64, K-chunk 128, 4-deep TMA pipeline,
// register-double-buffered ldsm (frags for ks+1 load under MMAs of ks).
// ============================================================================
static constexpr int A_SUB = 16384;   // A sub-tile: 128 rows x 128B
static constexpr int B_OFF = 32768;
static constexpr int B_SUB = 8192;    // B sub-tile: 64 rows x 128B
static constexpr int BUF   = 49152;
static constexpr int SM_TILES = 1024; // mbarriers live below
static constexpr int GEMM_SMEM = SM_TILES + 4 * BUF;   // 197632
static constexpr int NC    = I_DIM / 128;   // 32 chunks

__device__ __forceinline__ uint32_t smem_u32(const void* p) {
    uint32_t a;
    asm("{ .reg .u64 t; cvta.to.shared.u64 t, %1; cvt.u32.u64 %0, t; }"
        : "=r"(a) : "l"(p));
    return a;
}
__device__ __forceinline__ void ldsm4(uint32_t* r, uint32_t addr) {
    asm volatile("ldmatrix.sync.aligned.m8n8.x4.shared.b16 {%0,%1,%2,%3}, [%4];"
                 : "=r"(r[0]), "=r"(r[1]), "=r"(r[2]), "=r"(r[3]) : "r"(addr));
}
__device__ __forceinline__ void mma16816(float* c, const uint32_t* a,
                                         uint32_t b0, uint32_t b1) {
    asm volatile(
        "mma.sync.aligned.m16n8k16.row.col.f32.f16.f16.f32 "
        "{%0,%1,%2,%3}, {%4,%5,%6,%7}, {%8,%9}, {%0,%1,%2,%3};"
        : "+f"(c[0]), "+f"(c[1]), "+f"(c[2]), "+f"(c[3])
        : "r"(a[0]), "r"(a[1]), "r"(a[2]), "r"(a[3]), "r"(b0), "r"(b1));
}

#define MBAR_WAIT(mbar_addr, phase) do {                                         \
    uint32_t _mbar = (uint32_t)(mbar_addr);                                      \
    uint32_t _parity = (uint32_t)(phase);                                        \
    uint32_t _done;                                                              \
    asm volatile(                                                                \
        "{\n\t.reg .pred p;\n\t"                                                 \
        "mbarrier.try_wait.parity.acquire.cta.shared::cta.b64 p, [%1], %2;\n\t"  \
        "selp.b32 %0, 1, 0, p;\n\t}"                                             \
        : "=r"(_done) : "r"(_mbar), "r"(_parity) : "memory");                    \
    if (!_done) {                                                                \
        asm volatile(                                                            \
            "{\n\t.reg .pred P1;\n\t"                                            \
            "WL_%=:\n\t"                                                         \
            "mbarrier.try_wait.parity.acquire.cta.shared::cta.b64 P1, [%0], %1, 0x989680;\n\t" \
            "@P1 bra.uni WD_%=;\n\t"                                             \
            "bra.uni WL_%=;\n\t"                                                 \
            "WD_%=:\n\t}"                                                        \
            :: "r"(_mbar), "r"(_parity) : "memory");                             \
    }                                                                            \
} while (0)

// Issue A(32KB) + B(16KB) bulk copies for chunk c into buffer (single thread).
__device__ __forceinline__ void tma_chunk(uint32_t bufb, uint32_t mbar,
                                          int c, int m0, int n0) {
    asm volatile("mbarrier.arrive.expect_tx.shared.b64 _, [%0], %1;"
                 :: "r"(mbar), "r"(49152u) : "memory");
    const char* srcA = reinterpret_cast<const char*>(g_xh)
                     + (size_t)c * 65536 + (m0 >> 7) * 32768;
    const char* srcB = reinterpret_cast<const char*>(g_wh)
                     + (size_t)c * 1048576 + (n0 >> 6) * 16384;
    asm volatile(
        "cp.async.bulk.shared::cluster.global.mbarrier::complete_tx::bytes "
        "[%0], [%1], %2, [%3];"
        :: "r"(bufb), "l"(srcA), "r"(32768u), "r"(mbar) : "memory");
    asm volatile(
        "cp.async.bulk.shared::cluster.global.mbarrier::complete_tx::bytes "
        "[%0], [%1], %2, [%3];"
        :: "r"(bufb + B_OFF), "l"(srcB), "r"(16384u), "r"(mbar) : "memory");
}

__global__ void __launch_bounds__(256, 1) gemm_kernel(float* __restrict__ y) {
    extern __shared__ __align__(1024) char smem[];
    const uint32_t sb = smem_u32(smem);
    const int tid = threadIdx.x, lane = tid & 31, wid = tid >> 5;
    const int wm = wid >> 1, wn = wid & 1;          // warp grid 4(M) x 2(N)
    const int n0 = blockIdx.x * 64;
    const int m0 = blockIdx.y * 128;

    if (tid < 4)
        asm volatile("mbarrier.init.shared.b64 [%0], 1;"
                     :: "r"(sb + tid * 8) : "memory");
    __syncthreads();
    if (tid == 0) {
        tma_chunk(sb + SM_TILES + 0 * BUF, sb + 0,  0, m0, n0);
        tma_chunk(sb + SM_TILES + 1 * BUF, sb + 8,  1, m0, n0);
        tma_chunk(sb + SM_TILES + 2 * BUF, sb + 16, 2, m0, n0);
        tma_chunk(sb + SM_TILES + 3 * BUF, sb + 24, 3, m0, n0);
    }

    float acc[2][4][4];
    #pragma unroll
    for (int i = 0; i < 2; ++i)
        #pragma unroll
        for (int j = 0; j < 4; ++j)
            #pragma unroll
            for (int q = 0; q < 4; ++q) acc[i][j][q] = 0.f;

    const int rl = lane & 15;
    const uint32_t kh16 = (uint32_t)(lane >> 4) * 16;
    const uint32_t arow0 = (uint32_t)(wm * 32 + rl) * 128;
    const uint32_t arow1 = arow0 + 16 * 128;
    const uint32_t brow0 = (uint32_t)(wn * 32 + rl) * 128;
    const uint32_t brow1 = brow0 + 16 * 128;

    for (int c = 0; c < NC; ++c) {
        const int b = c & 3;
        MBAR_WAIT(sb + b * 8, (c >> 2) & 1);
        const uint32_t bb = sb + SM_TILES + b * BUF;

        // register-double-buffered frags: load ks+1 while MMAs of ks run
        uint32_t ah[2][2][4], bh[2][2][4];
        {
            const uint32_t kb = kh16;
            ldsm4(ah[0][0], bb + SW128(arow0 + kb));
            ldsm4(ah[0][1], bb + SW128(arow1 + kb));
            ldsm4(bh[0][0], bb + B_OFF + SW128(brow0 + kb));
            ldsm4(bh[0][1], bb + B_OFF + SW128(brow1 + kb));
        }
        #pragma unroll
        for (int ks = 0; ks < 8; ++ks) {
            const int cur = ks & 1, nxt = cur ^ 1;
            if (ks < 7) {
                const int kn = ks + 1;
                const uint32_t sub_a = bb + (kn >> 2) * A_SUB;
                const uint32_t sub_b = bb + B_OFF + (kn >> 2) * B_SUB;
                const uint32_t kb = (uint32_t)(kn & 3) * 32 + kh16;
                ldsm4(ah[nxt][0], sub_a + SW128(arow0 + kb));
                ldsm4(ah[nxt][1], sub_a + SW128(arow1 + kb));
                ldsm4(bh[nxt][0], sub_b + SW128(brow0 + kb));
                ldsm4(bh[nxt][1], sub_b + SW128(brow1 + kb));
            }
            #pragma unroll
            for (int mi = 0; mi < 2; ++mi)
                #pragma unroll
                for (int nj = 0; nj < 2; ++nj) {
                    mma16816(acc[mi][nj*2+0], ah[cur][mi], bh[cur][nj][0], bh[cur][nj][2]);
                    mma16816(acc[mi][nj*2+1], ah[cur][mi], bh[cur][nj][1], bh[cur][nj][3]);
                }
        }
        __syncthreads();   // all warps done with buffer b
        if (tid == 0 && c + 4 < NC)
            tma_chunk(sb + SM_TILES + b * BUF, sb + b * 8, c + 4, m0, n0);
    }

    #pragma unroll
    for (int mi = 0; mi < 2; ++mi) {
        const int row0 = m0 + wm * 32 + mi * 16 + (lane >> 2);
        #pragma unroll
        for (int nb = 0; nb < 4; ++nb) {
            const int col = n0 + wn * 32 + nb * 8 + (lane & 3) * 2;
            *reinterpret_cast<float2*>(y + (size_t)row0 * O_DIM + col) =
                make_float2(acc[mi][nb][0], acc[mi][nb][1]);
            *reinterpret_cast<float2*>(y + (size_t)(row0 + 8) * O_DIM + col) =
                make_float2(acc[mi][nb][2], acc[mi][nb][3]);
        }
    }
}

// ============================================================================
extern "C" void kernel_launch(void* const* d_in, const int* in_sizes, int n_in,
                              void* d_out, int out_size) {
    const float* x    = (const float*)d_in[0];
    const float* w    = (const float*)d_in[1];
    const int*   flip = (const int*)d_in[2];   // JAX x64 disabled -> int32
    const float* vals = (const float*)d_in[3];
    float*       y    = (float*)d_out;
    const int nflip = in_sizes[2];

    stage1_kernel<<<NB_WIN + NB_CX + NB_CW, 256>>>(
        reinterpret_cast<const float4*>(x), reinterpret_cast<const float4*>(w),
        flip, nflip);
    scatter_kernel<<<(nflip + 2047) / 2048, 256>>>(flip, vals, nflip);

    cudaFuncSetAttribute(gemm_kernel, cudaFuncAttributeMaxDynamicSharedMemorySize,
                         GEMM_SMEM);
    gemm_kernel<<<dim3(O_DIM / 64, B_ROWS / 128, 1), 256, GEMM_SMEM>>>(y);
}